// round 2
// baseline (speedup 1.0000x reference)
#include <cuda_runtime.h>

#define TB      64      // batch rows per CTA
#define THREADS 256
#define HID     256
#define ND      64      // num dense features

// h_sh / d_sh row stride in floats (even -> b64-aligned pairs)
#define DST     68
#define HST     68

// --- packed f32x2 helpers (sm_103a FFMA2 path; ptxas never auto-fuses) ---
__device__ __forceinline__ unsigned long long pack2(float lo, float hi) {
    unsigned long long r;
    asm("mov.b64 %0, {%1, %2};" : "=l"(r) : "f"(lo), "f"(hi));
    return r;
}
__device__ __forceinline__ void unpack2(unsigned long long v, float& lo, float& hi) {
    asm("mov.b64 {%0, %1}, %2;" : "=f"(lo), "=f"(hi) : "l"(v));
}
__device__ __forceinline__ unsigned long long fma2(unsigned long long a, unsigned long long b,
                                                   unsigned long long c) {
    unsigned long long d;
    asm("fma.rn.f32x2 %0, %1, %2, %3;" : "=l"(d) : "l"(a), "l"(b), "l"(c));
    return d;
}
__device__ __forceinline__ unsigned long long add2(unsigned long long a, unsigned long long b) {
    unsigned long long d;
    asm("add.rn.f32x2 %0, %1, %2;" : "=l"(d) : "l"(a), "l"(b));
    return d;
}

__global__ __launch_bounds__(THREADS, 2)
void ddm_fused_kernel(const float* __restrict__ dense,
                      const int* __restrict__ sparse_i32,   // raw words; dtype autodetected
                      const float* __restrict__ W1,
                      const float* __restrict__ b1,
                      const float* __restrict__ W2,
                      const float* __restrict__ b2,
                      float* __restrict__ out) {
    // cumulative one-hot block offsets: 64 + prefix(CARDS)
    const int OFFS[8] = {64, 1064, 1564, 1764, 1864, 1914, 1964, 1984};

    extern __shared__ float smem[];
    float* d_sh    = smem;                         // [64][DST]   dense transposed
    int*   rows_sh = (int*)(smem + 64 * DST);      // [TB][8]     gather row ids
    float* h_sh    = smem + 64 * DST + TB * 8;     // [256][HST]  hidden transposed

    const int tid = threadIdx.x;
    const int b0  = blockIdx.x * TB;

    // ---- dtype autodetect: values are in [0,10). If buffer is int64 (LE),
    // every odd int32 word of the first 64 elements is 0. If int32, odd words
    // are random in [0,10) -> P(all zero) ~ 1e-64. Same result in every thread.
    int odd_or = 0;
#pragma unroll
    for (int i = 0; i < 64; i++) odd_or |= __ldg(&sparse_i32[2 * i + 1]);
    const int is64 = (odd_or == 0);

    // ---- stage dense tile transposed: d_sh[k][b] = dense[b0+b][k] ----
    for (int i = tid; i < TB * ND; i += THREADS) {
        int b = i >> 6, k = i & 63;
        d_sh[k * DST + b] = dense[(size_t)b0 * ND + i];
    }
    // ---- stage gather rows (clamped as a safety net) ----
    for (int i = tid; i < TB * 8; i += THREADS) {
        int f = i & 7;
        size_t gidx = (size_t)b0 * 8 + i;
        int v = is64 ? sparse_i32[2 * gidx] : sparse_i32[gidx];
        int r = OFFS[f] + v;
        rows_sh[i] = min(max(r, 0), 1993);
    }
    __syncthreads();

    // thread tiling: 2 columns (j0, j0+128) x 32 rows
    const int tx = tid & 127;
    const int ty = tid >> 7;
    const int j0 = tx, j1 = tx + 128;
    const int r0 = ty * 32;

    unsigned long long accA[16], accB[16];

    // ================= Phase 1: h = relu(dense@W1[0:64] + gathers + b1) =================
    {
        float ba = b1[j0], bb = b1[j1];
        unsigned long long pa = pack2(ba, ba), pb = pack2(bb, bb);
#pragma unroll
        for (int p = 0; p < 16; p++) { accA[p] = pa; accB[p] = pb; }
    }

#pragma unroll 8
    for (int k = 0; k < ND; k++) {
        float w0 = W1[(size_t)k * HID + j0];
        float w1 = W1[(size_t)k * HID + j1];
        unsigned long long w0p = pack2(w0, w0), w1p = pack2(w1, w1);
        const unsigned long long* dp =
            (const unsigned long long*)(d_sh + k * DST + r0);   // broadcast b64 loads
#pragma unroll
        for (int p = 0; p < 16; p++) {
            unsigned long long dv = dp[p];
            accA[p] = fma2(dv, w0p, accA[p]);
            accB[p] = fma2(dv, w1p, accB[p]);
        }
    }

    // gathers: + sum_f W1[row_f(b)][j]  (indices < 1994, hot rows stay in L1/L2)
    {
        const int* rp = rows_sh + r0 * 8;
#pragma unroll 2
        for (int i = 0; i < 32; i += 2) {
#pragma unroll
            for (int f = 0; f < 8; f++) {
                int ra = rp[i * 8 + f];
                int rb = rp[(i + 1) * 8 + f];
                float gA0 = W1[(size_t)ra * HID + j0];
                float gA1 = W1[(size_t)rb * HID + j0];
                float gB0 = W1[(size_t)ra * HID + j1];
                float gB1 = W1[(size_t)rb * HID + j1];
                accA[i >> 1] = add2(pack2(gA0, gA1), accA[i >> 1]);
                accB[i >> 1] = add2(pack2(gB0, gB1), accB[i >> 1]);
            }
        }
    }

    // relu + store h transposed: h_sh[j][b]
#pragma unroll
    for (int p = 0; p < 16; p++) {
        float x0, x1;
        unpack2(accA[p], x0, x1);
        x0 = fmaxf(x0, 0.f); x1 = fmaxf(x1, 0.f);
        *(float2*)&h_sh[j0 * HST + r0 + 2 * p] = make_float2(x0, x1);
        unpack2(accB[p], x0, x1);
        x0 = fmaxf(x0, 0.f); x1 = fmaxf(x1, 0.f);
        *(float2*)&h_sh[j1 * HST + r0 + 2 * p] = make_float2(x0, x1);
    }
    __syncthreads();

    // ================= Phase 2: out = h @ W2 + b2 =================
    {
        float ba = b2[j0], bb = b2[j1];
        unsigned long long pa = pack2(ba, ba), pb = pack2(bb, bb);
#pragma unroll
        for (int p = 0; p < 16; p++) { accA[p] = pa; accB[p] = pb; }
    }

#pragma unroll 4
    for (int jj = 0; jj < HID; jj++) {
        float w0 = W2[(size_t)jj * HID + j0];
        float w1 = W2[(size_t)jj * HID + j1];
        unsigned long long w0p = pack2(w0, w0), w1p = pack2(w1, w1);
        const unsigned long long* hp =
            (const unsigned long long*)(h_sh + jj * HST + r0);  // broadcast b64 loads
#pragma unroll
        for (int p = 0; p < 16; p++) {
            unsigned long long hv = hp[p];
            accA[p] = fma2(hv, w0p, accA[p]);
            accB[p] = fma2(hv, w1p, accB[p]);
        }
    }

    // write out (coalesced across tx per row)
#pragma unroll
    for (int p = 0; p < 16; p++) {
        float x0, x1;
        size_t rowa = (size_t)(b0 + r0 + 2 * p) * HID;
        size_t rowb = rowa + HID;
        unpack2(accA[p], x0, x1);
        out[rowa + j0] = x0;
        out[rowb + j0] = x1;
        unpack2(accB[p], x0, x1);
        out[rowa + j1] = x0;
        out[rowb + j1] = x1;
    }
}

extern "C" void kernel_launch(void* const* d_in, const int* in_sizes, int n_in,
                              void* d_out, int out_size) {
    const float* dense  = (const float*)d_in[0];
    const int*   sparse = (const int*)d_in[1];
    const float* W1     = (const float*)d_in[2];
    const float* b1     = (const float*)d_in[3];
    const float* W2     = (const float*)d_in[4];
    const float* b2     = (const float*)d_in[5];
    float*       out    = (float*)d_out;

    int B = in_sizes[0] / ND;                 // 16384
    int grid = B / TB;                        // 256 CTAs

    int smem_bytes = (64 * DST) * 4 + TB * 8 * 4 + (HID * HST) * 4;  // 89088 B
    cudaFuncSetAttribute(ddm_fused_kernel,
                         cudaFuncAttributeMaxDynamicSharedMemorySize, smem_bytes);

    ddm_fused_kernel<<<grid, THREADS, smem_bytes>>>(dense, sparse, W1, b1, W2, b2, out);
}

// round 3
// speedup vs baseline: 1.2035x; 1.2035x over previous
#include <cuda_runtime.h>

#define TB      64      // batch rows per CTA
#define THREADS 256
#define HID     256
#define ND      64      // num dense features

#define DST     68      // dense smem row stride (floats, even)
#define HST     68      // hidden smem row stride (floats, even)

// --- packed f32x2 helpers (sm_103a FFMA2 path; ptxas never auto-fuses) ---
__device__ __forceinline__ unsigned long long pack2(float lo, float hi) {
    unsigned long long r;
    asm("mov.b64 %0, {%1, %2};" : "=l"(r) : "f"(lo), "f"(hi));
    return r;
}
__device__ __forceinline__ void unpack2(unsigned long long v, float& lo, float& hi) {
    asm("mov.b64 {%0, %1}, %2;" : "=f"(lo), "=f"(hi) : "l"(v));
}
__device__ __forceinline__ unsigned long long fma2(unsigned long long a, unsigned long long b,
                                                   unsigned long long c) {
    unsigned long long d;
    asm("fma.rn.f32x2 %0, %1, %2, %3;" : "=l"(d) : "l"(a), "l"(b), "l"(c));
    return d;
}
__device__ __forceinline__ unsigned long long add2(unsigned long long a, unsigned long long b) {
    unsigned long long d;
    asm("add.rn.f32x2 %0, %1, %2;" : "=l"(d) : "l"(a), "l"(b));
    return d;
}

__global__ __launch_bounds__(THREADS, 2)
void ddm_fused_kernel(const float* __restrict__ dense,
                      const int* __restrict__ sparse_i32,   // raw words; dtype autodetected
                      const float* __restrict__ W1,
                      const float* __restrict__ b1,
                      const float* __restrict__ W2,
                      const float* __restrict__ b2,
                      float* __restrict__ out) {
    // cumulative one-hot block offsets: 64 + prefix(CARDS)
    const int OFFS[8] = {64, 1064, 1564, 1764, 1864, 1914, 1964, 1984};

    extern __shared__ float smem[];
    float* d_sh    = smem;                         // [64][DST]   dense transposed
    int*   rows_sh = (int*)(smem + 64 * DST);      // [TB][8]     gather row ids
    float* h_sh    = smem + 64 * DST + TB * 8;     // [256][HST]  hidden transposed

    const int tid = threadIdx.x;
    const int b0  = blockIdx.x * TB;

    // ---- dtype autodetect: values in [0,10). int64(LE) -> every odd i32 word
    // of the first 64 elements is 0; int32 -> P(all zero) ~ 1e-64.
    int odd_or = 0;
#pragma unroll
    for (int i = 0; i < 64; i++) odd_or |= __ldg(&sparse_i32[2 * i + 1]);
    const int is64 = (odd_or == 0);

    // ---- stage dense tile transposed: d_sh[k][b] = dense[b0+b][k] ----
    for (int i = tid; i < TB * ND; i += THREADS) {
        int b = i >> 6, k = i & 63;
        d_sh[k * DST + b] = dense[(size_t)b0 * ND + i];
    }
    // ---- stage gather rows (clamped as a safety net) ----
    for (int i = tid; i < TB * 8; i += THREADS) {
        int f = i & 7;
        size_t gidx = (size_t)b0 * 8 + i;
        int v = is64 ? sparse_i32[2 * gidx] : sparse_i32[gidx];
        int r = OFFS[f] + v;
        rows_sh[i] = min(max(r, 0), 1993);
    }
    __syncthreads();

    // thread tiling: 4 consecutive cols (c0..c0+3) x 16 rows
    const int tx = tid & 63;
    const int ty = tid >> 6;          // 0..3
    const int c0 = tx * 4;
    const int r0 = ty * 16;

    unsigned long long acc[4][8];     // [col][row-pair]

    // ================= Phase 1: h = relu(dense@W1[0:64] + gathers + b1) =================
    {
        float4 b = *(const float4*)&b1[c0];
        acc[0][0] = pack2(b.x, b.x); acc[1][0] = pack2(b.y, b.y);
        acc[2][0] = pack2(b.z, b.z); acc[3][0] = pack2(b.w, b.w);
#pragma unroll
        for (int p = 1; p < 8; p++) {
            acc[0][p] = acc[0][0]; acc[1][p] = acc[1][0];
            acc[2][p] = acc[2][0]; acc[3][p] = acc[3][0];
        }
    }

#pragma unroll 4
    for (int k = 0; k < ND; k++) {
        float4 w = *(const float4*)&W1[(size_t)k * HID + c0];   // LDG.128
        unsigned long long wp[4] = { pack2(w.x, w.x), pack2(w.y, w.y),
                                     pack2(w.z, w.z), pack2(w.w, w.w) };
        const unsigned long long* dp =
            (const unsigned long long*)(d_sh + k * DST + r0);   // broadcast b64 loads
#pragma unroll
        for (int p = 0; p < 8; p++) {
            unsigned long long dv = dp[p];
#pragma unroll
            for (int c = 0; c < 4; c++) acc[c][p] = fma2(dv, wp[c], acc[c][p]);
        }
    }

    // gathers: + sum_f W1[row_f(b)][c]  (all lanes share row -> coalesced LDG.128)
    {
        const int* rp = rows_sh + r0 * 8;
#pragma unroll
        for (int p = 0; p < 8; p++) {
#pragma unroll
            for (int f = 0; f < 8; f++) {
                int ra = rp[(2 * p) * 8 + f];
                int rb = rp[(2 * p + 1) * 8 + f];
                float4 ga = *(const float4*)&W1[(size_t)ra * HID + c0];
                float4 gb = *(const float4*)&W1[(size_t)rb * HID + c0];
                acc[0][p] = add2(pack2(ga.x, gb.x), acc[0][p]);
                acc[1][p] = add2(pack2(ga.y, gb.y), acc[1][p]);
                acc[2][p] = add2(pack2(ga.z, gb.z), acc[2][p]);
                acc[3][p] = add2(pack2(ga.w, gb.w), acc[3][p]);
            }
        }
    }

    // relu + store h transposed: h_sh[col][row]
#pragma unroll
    for (int p = 0; p < 8; p++) {
#pragma unroll
        for (int c = 0; c < 4; c++) {
            float x0, x1;
            unpack2(acc[c][p], x0, x1);
            x0 = fmaxf(x0, 0.f); x1 = fmaxf(x1, 0.f);
            *(float2*)&h_sh[(c0 + c) * HST + r0 + 2 * p] = make_float2(x0, x1);
        }
    }
    __syncthreads();

    // ================= Phase 2: out = h @ W2 + b2 =================
    {
        float4 b = *(const float4*)&b2[c0];
        acc[0][0] = pack2(b.x, b.x); acc[1][0] = pack2(b.y, b.y);
        acc[2][0] = pack2(b.z, b.z); acc[3][0] = pack2(b.w, b.w);
#pragma unroll
        for (int p = 1; p < 8; p++) {
            acc[0][p] = acc[0][0]; acc[1][p] = acc[1][0];
            acc[2][p] = acc[2][0]; acc[3][p] = acc[3][0];
        }
    }

#pragma unroll 4
    for (int jj = 0; jj < HID; jj++) {
        float4 w = *(const float4*)&W2[(size_t)jj * HID + c0];  // LDG.128
        unsigned long long wp[4] = { pack2(w.x, w.x), pack2(w.y, w.y),
                                     pack2(w.z, w.z), pack2(w.w, w.w) };
        const unsigned long long* hp =
            (const unsigned long long*)(h_sh + jj * HST + r0);  // broadcast b64 loads
#pragma unroll
        for (int p = 0; p < 8; p++) {
            unsigned long long hv = hp[p];
#pragma unroll
            for (int c = 0; c < 4; c++) acc[c][p] = fma2(hv, wp[c], acc[c][p]);
        }
    }

    // write out: two float4 stores per row-pair (coalesced across tx)
#pragma unroll
    for (int p = 0; p < 8; p++) {
        float a0, a1, b0f, b1f, c0f, c1f, d0, d1;
        unpack2(acc[0][p], a0, a1);
        unpack2(acc[1][p], b0f, b1f);
        unpack2(acc[2][p], c0f, c1f);
        unpack2(acc[3][p], d0, d1);
        size_t rowa = (size_t)(b0 + r0 + 2 * p) * HID;
        size_t rowb = rowa + HID;
        *(float4*)&out[rowa + c0] = make_float4(a0, b0f, c0f, d0);
        *(float4*)&out[rowb + c0] = make_float4(a1, b1f, c1f, d1);
    }
}

extern "C" void kernel_launch(void* const* d_in, const int* in_sizes, int n_in,
                              void* d_out, int out_size) {
    const float* dense  = (const float*)d_in[0];
    const int*   sparse = (const int*)d_in[1];
    const float* W1     = (const float*)d_in[2];
    const float* b1     = (const float*)d_in[3];
    const float* W2     = (const float*)d_in[4];
    const float* b2     = (const float*)d_in[5];
    float*       out    = (float*)d_out;

    int B = in_sizes[0] / ND;                 // 16384
    int grid = B / TB;                        // 256 CTAs

    int smem_bytes = (64 * DST) * 4 + TB * 8 * 4 + (HID * HST) * 4;  // 89088 B
    cudaFuncSetAttribute(ddm_fused_kernel,
                         cudaFuncAttributeMaxDynamicSharedMemorySize, smem_bytes);

    ddm_fused_kernel<<<grid, THREADS, smem_bytes>>>(dense, sparse, W1, b1, W2, b2, out);
}